// round 14
// baseline (speedup 1.0000x reference)
#include <cuda_runtime.h>
#include <cuda_fp16.h>
#include <math.h>

#define B_   2
#define S_   2048
#define HID_ 1024
#define NH_  16
#define HD_  64
#define M_   (B_ * S_)        // 4096
#define QKV_N (3 * HID_)      // 3072
#define QKV_TILES (24 * 32)   // 768
#define ATTN_TICKETS 512      // 16 q-blocks x 32 bh

// ---------------- scratch (device globals) ---------------------------------
__device__ __half g_q[B_ * NH_ * S_ * HD_];    // [b,h,s,d] fp16, pre-scaled
__device__ __half g_k[B_ * NH_ * S_ * HD_];
__device__ __half g_v[B_ * NH_ * S_ * HD_];
__device__ __half g_attno[M_ * HID_];          // [b,s,hid] fp16
__device__ float  g_cos[S_ * HD_];
__device__ float  g_sin[S_ * HD_];
__device__ __half g_hid_h[M_ * HID_];          // fp16 [M,K]
__device__ __half g_wqkv_t[QKV_N * HID_];      // [N,K] fp16 (transposed)
__device__ __half g_wdense_t[HID_ * HID_];     // [N,K] fp16 (transposed)
__device__ unsigned g_qkv_ctr;                 // persistent-GEMM ticket
__device__ unsigned g_attn_ctr;                // persistent-attention ticket

// ---------------- helpers ---------------------------------------------------
__device__ __forceinline__ float ex2(float x) {
    float r;
    asm("ex2.approx.f32 %0, %1;" : "=f"(r) : "f"(x));
    return r;
}
__device__ __forceinline__ unsigned packh2(float a, float b) {
    __half2 h = __floats2half2_rn(a, b);
    return *(unsigned*)&h;
}
__device__ __forceinline__ void mma_f16(float* c, const unsigned* a,
                                        unsigned b0, unsigned b1) {
    asm volatile(
        "mma.sync.aligned.m16n8k16.row.col.f32.f16.f16.f32 "
        "{%0,%1,%2,%3}, {%4,%5,%6,%7}, {%8,%9}, {%0,%1,%2,%3};\n"
        : "+f"(c[0]), "+f"(c[1]), "+f"(c[2]), "+f"(c[3])
        : "r"(a[0]), "r"(a[1]), "r"(a[2]), "r"(a[3]), "r"(b0), "r"(b1));
}
__device__ __forceinline__ void ldsm_x4(unsigned* r, unsigned saddr) {
    asm volatile("ldmatrix.sync.aligned.m8n8.x4.shared.b16 {%0,%1,%2,%3}, [%4];"
                 : "=r"(r[0]), "=r"(r[1]), "=r"(r[2]), "=r"(r[3]) : "r"(saddr));
}
__device__ __forceinline__ void ldsm_x4_t(unsigned* r, unsigned saddr) {
    asm volatile("ldmatrix.sync.aligned.m8n8.x4.trans.shared.b16 {%0,%1,%2,%3}, [%4];"
                 : "=r"(r[0]), "=r"(r[1]), "=r"(r[2]), "=r"(r[3]) : "r"(saddr));
}
__device__ __forceinline__ void cp16s(unsigned saddr, const void* gmem) {
    asm volatile("cp.async.cg.shared.global [%0], [%1], 16;" :: "r"(saddr), "l"(gmem));
}
#define CP_COMMIT asm volatile("cp.async.commit_group;")
#define CP_WAIT0  asm volatile("cp.async.wait_group 0;")
#define CP_WAIT1  asm volatile("cp.async.wait_group 1;")

// ---------------- merged prep kernel (hidden cvt + rope + tickets) ----------
#define PREP_N1 (M_ * HID_ / 4)                  // 1048576
#define PREP_N2 (PREP_N1 + S_ * HD_)             // 1179648

__global__ void prep_kernel(const float* __restrict__ hidden) {
    int i = blockIdx.x * blockDim.x + threadIdx.x;
    if (i == 0) { g_qkv_ctr = 0; g_attn_ctr = 0; }
    if (i < PREP_N1) {
        float4 f = ((const float4*)hidden)[i];
        ((uint2*)g_hid_h)[i] = make_uint2(packh2(f.x, f.y), packh2(f.z, f.w));
    } else if (i < PREP_N2) {
        int idx = i - PREP_N1;
        int s = idx >> 6;
        int d = idx & 63;
        int k = d & 31;
        double inv = pow(10000.0, -((double)(2 * k)) / (double)HD_);
        float freq = (float)s * (float)inv;
        g_cos[idx] = (float)cos((double)freq);
        g_sin[idx] = (float)sin((double)freq);
    }
}

// ---------------- merged weight transpose ------------------------------------
#define TQKV_BLKS (96 * 32)
#define TTOT_BLKS (TQKV_BLKS + 32 * 32)

__global__ void transpose_both_kernel(const float* __restrict__ wqkv,
                                      const float* __restrict__ wdense) {
    __shared__ float t[32][33];
    int bid = blockIdx.x;
    const float* in;
    __half* out;
    int R = HID_, C;
    int bx, by;
    if (bid < TQKV_BLKS) {
        in = wqkv; out = g_wqkv_t; C = QKV_N;
        bx = bid % 96; by = bid / 96;
    } else {
        in = wdense; out = g_wdense_t; C = HID_;
        int b2 = bid - TQKV_BLKS;
        bx = b2 % 32; by = b2 / 32;
    }
    int rb = by * 32, cb = bx * 32;
    int tx = threadIdx.x, ty = threadIdx.y;
#pragma unroll
    for (int i = ty; i < 32; i += 8)
        t[i][tx] = in[(size_t)(rb + i) * C + cb + tx];
    __syncthreads();
#pragma unroll
    for (int i = ty; i < 32; i += 8)
        out[(size_t)(cb + i) * R + rb + tx] = __float2half_rn(t[tx][i]);
}

// ---------------- fp16 GEMM mainloop (BK=64, double-buffered) ----------------
#define GROW 144                    // bytes per smem row (64 halfs + 16B pad)
#define GBUF (128 * GROW)           // 18432 bytes per tile buffer

__device__ __forceinline__ void gemm16_main(
    const __half* __restrict__ A, const __half* __restrict__ Wt,
    int row0, int col0, unsigned smem_base, float acc[2][8][4],
    int tid, int lane, int wm, int wn)
{
#pragma unroll
    for (int mt = 0; mt < 2; mt++)
#pragma unroll
        for (int nt = 0; nt < 8; nt++)
#pragma unroll
            for (int j = 0; j < 4; j++) acc[mt][nt][j] = 0.0f;

    auto load_tile = [&](int st, int t) {
        int k0 = t * 64;
        unsigned sa = smem_base + st * GBUF;
        unsigned sb = smem_base + 2 * GBUF + st * GBUF;
#pragma unroll
        for (int it = 0; it < 4; it++) {
            int id = tid + it * 256;          // 0..1023
            int r = id >> 3, ch = id & 7;
            cp16s(sa + r * GROW + ch * 16,
                  &A[(size_t)(row0 + r) * HID_ + k0 + ch * 8]);
        }
#pragma unroll
        for (int it = 0; it < 4; it++) {
            int id = tid + it * 256;
            int r = id >> 3, ch = id & 7;
            cp16s(sb + r * GROW + ch * 16,
                  &Wt[(size_t)(col0 + r) * HID_ + k0 + ch * 8]);
        }
    };

    load_tile(0, 0); CP_COMMIT;

    for (int t = 0; t < 16; t++) {
        int st = t & 1;
        if (t + 1 < 16) { load_tile(st ^ 1, t + 1); CP_COMMIT; CP_WAIT1; }
        else            { CP_WAIT0; }
        __syncthreads();

        unsigned sa = smem_base + st * GBUF;
        unsigned sb = smem_base + 2 * GBUF + st * GBUF;
#pragma unroll
        for (int ks = 0; ks < 4; ks++) {
            unsigned a[2][4];
#pragma unroll
            for (int mt = 0; mt < 2; mt++) {
                unsigned addr = sa + (wm + mt * 16 + (lane & 15)) * GROW
                              + ks * 32 + (lane >> 4) * 16;
                ldsm_x4(a[mt], addr);
            }
            unsigned b[8][2];
#pragma unroll
            for (int ntp = 0; ntp < 4; ntp++) {
                int nrow = wn + ntp * 16 + (lane & 7) + ((lane >> 4) << 3);
                unsigned addr = sb + nrow * GROW + ks * 32 + ((lane >> 3) & 1) * 16;
                unsigned r[4];
                ldsm_x4(r, addr);
                b[2 * ntp][0]     = r[0]; b[2 * ntp][1]     = r[1];
                b[2 * ntp + 1][0] = r[2]; b[2 * ntp + 1][1] = r[3];
            }
#pragma unroll
            for (int mt = 0; mt < 2; mt++)
#pragma unroll
                for (int nt = 0; nt < 8; nt++)
                    mma_f16(acc[mt][nt], a[mt], b[nt][0], b[nt][1]);
        }
        __syncthreads();
    }
}

// ---------------- QKV GEMM (persistent) + fused RoPE/split epilogue ---------
__global__ __launch_bounds__(256, 2)
void gemm16_qkv(const __half* __restrict__ A, const __half* __restrict__ Wt) {
    extern __shared__ char dsm[];
    __shared__ int s_tile;
    unsigned smem_base = (unsigned)__cvta_generic_to_shared(dsm);
    int tid = threadIdx.x, lane = tid & 31, warp = tid >> 5;
    int wm = (warp & 3) * 32;
    int wn = (warp >> 2) * 64;
    const float QS = 0.125f * 1.4426950408889634f;

    for (;;) {
        if (tid == 0) s_tile = (int)atomicAdd(&g_qkv_ctr, 1u);
        __syncthreads();
        int t = s_tile;
        if (t >= QKV_TILES) break;
        int row0 = (t & 31) * 128;
        int col0 = (t >> 5) * 128;

        float acc[2][8][4];
        gemm16_main(A, Wt, row0, col0, smem_base, acc, tid, lane, wm, wn);

        int region = col0 >> 10;                 // 0=q 1=k 2=v
        int h      = ((col0 & 1023) + wn) >> 6;  // warp covers one head

#pragma unroll
        for (int mt = 0; mt < 2; mt++) {
            int r = row0 + wm + mt * 16 + (lane >> 2);
            int b = r >> 11, s = r & 2047;
            size_t base_lo = ((size_t)((b << 4) + h) * S_ + s) * 64;
            size_t base_hi = base_lo + 8 * 64;

            if (region == 2) {
#pragma unroll
                for (int nt = 0; nt < 8; nt++) {
                    int d = nt * 8 + 2 * (lane & 3);
                    *(unsigned*)&g_v[base_lo + d] =
                        packh2(acc[mt][nt][0], acc[mt][nt][1]);
                    *(unsigned*)&g_v[base_hi + d] =
                        packh2(acc[mt][nt][2], acc[mt][nt][3]);
                }
            } else {
                __half* dst = (region == 0) ? g_q : g_k;
                float SC    = (region == 0) ? QS : 1.0f;
#pragma unroll
                for (int nt = 0; nt < 4; nt++) {
                    int d = nt * 8 + 2 * (lane & 3);    // d < 32
                    float2 cl = *(const float2*)&g_cos[s * 64 + d];
                    float2 sl = *(const float2*)&g_sin[s * 64 + d];
                    float2 ch = *(const float2*)&g_cos[(s + 8) * 64 + d];
                    float2 sh = *(const float2*)&g_sin[(s + 8) * 64 + d];

                    float x0 = acc[mt][nt][0],     x1 = acc[mt][nt][1];
                    float x2 = acc[mt][nt][2],     x3 = acc[mt][nt][3];
                    float y0 = acc[mt][nt + 4][0], y1 = acc[mt][nt + 4][1];
                    float y2 = acc[mt][nt + 4][2], y3 = acc[mt][nt + 4][3];

                    *(unsigned*)&dst[base_lo + d] =
                        packh2((x0 * cl.x - y0 * sl.x) * SC,
                               (x1 * cl.y - y1 * sl.y) * SC);
                    *(unsigned*)&dst[base_lo + d + 32] =
                        packh2((y0 * cl.x + x0 * sl.x) * SC,
                               (y1 * cl.y + x1 * sl.y) * SC);
                    *(unsigned*)&dst[base_hi + d] =
                        packh2((x2 * ch.x - y2 * sh.x) * SC,
                               (x3 * ch.y - y3 * sh.y) * SC);
                    *(unsigned*)&dst[base_hi + d + 32] =
                        packh2((y2 * ch.x + x2 * sh.x) * SC,
                               (y3 * ch.y + x3 * sh.y) * SC);
                }
            }
        }
    }
}

// ---------------- dense GEMM + bias (fp32 out) -------------------------------
__global__ __launch_bounds__(256, 2)
void gemm16_dense(const __half* __restrict__ A, const __half* __restrict__ Wt,
                  const float* __restrict__ bias, float* __restrict__ C) {
    extern __shared__ char dsm[];
    unsigned smem_base = (unsigned)__cvta_generic_to_shared(dsm);
    int tid = threadIdx.x, lane = tid & 31, warp = tid >> 5;
    int row0 = blockIdx.y * 128;
    int col0 = blockIdx.x * 128;
    int wm = (warp & 3) * 32;
    int wn = (warp >> 2) * 64;

    float acc[2][8][4];
    gemm16_main(A, Wt, row0, col0, smem_base, acc, tid, lane, wm, wn);

#pragma unroll
    for (int mt = 0; mt < 2; mt++) {
        int r = row0 + wm + mt * 16 + (lane >> 2);
#pragma unroll
        for (int nt = 0; nt < 8; nt++) {
            int c = col0 + wn + nt * 8 + 2 * (lane & 3);
            float bx = bias[c], by = bias[c + 1];
            float2 lo, hi;
            lo.x = acc[mt][nt][0] + bx; lo.y = acc[mt][nt][1] + by;
            hi.x = acc[mt][nt][2] + bx; hi.y = acc[mt][nt][3] + by;
            *(float2*)&C[(size_t)r * HID_ + c]       = lo;
            *(float2*)&C[(size_t)(r + 8) * HID_ + c] = hi;
        }
    }
}

// ---------------- causal flash attention (persistent, 128-token stages) ------
// 296 CTAs; 512 tickets, heaviest q-blocks first: qblk = 15 - tk/32, bh = tk%32.
// Each smem stage holds 128 KV tokens; two 64-token sub-tiles computed per
// barrier pair (sub-tile-1 S-MMAs overlap sub-tile-0 softmax drain).
#define AROW 144
#define ABUF2 (128 * AROW)          // 18432 per stage buffer

__global__ __launch_bounds__(256, 2)
void attn16(__half* __restrict__ Out) {
    extern __shared__ char dsm[];
    __shared__ int s_tk;
    unsigned smem_base = (unsigned)__cvta_generic_to_shared(dsm);
    unsigned kb_base = smem_base;                // K: [2][ABUF2]
    unsigned vb_base = smem_base + 2 * ABUF2;    // V: [2][ABUF2]

    int tid  = threadIdx.x;
    int lane = tid & 31;
    int warp = tid >> 5;

    for (;;) {
        if (tid == 0) s_tk = (int)atomicAdd(&g_attn_ctr, 1u);
        __syncthreads();
        int tk = s_tk;
        if (tk >= ATTN_TICKETS) break;
        int qblk = 15 - (tk >> 5);              // heaviest first
        int bh   = tk & 31;
        int b = bh >> 4, h = bh & 15;

        const __half* Qb = g_q + (size_t)bh * S_ * HD_;
        const __half* Kb = g_k + (size_t)bh * S_ * HD_;
        const __half* Vb = g_v + (size_t)bh * S_ * HD_;

        int qb   = qblk * 128;
        int qt2  = qblk * 2;
        int n128 = qblk + 1;                    // 128-token stages
        int row_lo  = qb + warp * 16 + (lane >> 2);
        int row_top = qb + warp * 16 + 15;

        unsigned qf[4][4];
#pragma unroll
        for (int ks = 0; ks < 4; ks++) {
            const __half* qp = Qb + (size_t)row_lo * 64 + ks * 16 + 2 * (lane & 3);
            qf[ks][0] = *(const unsigned*)(qp);
            qf[ks][1] = *(const unsigned*)(qp + 8 * 64);
            qf[ks][2] = *(const unsigned*)(qp + 8);
            qf[ks][3] = *(const unsigned*)(qp + 8 * 64 + 8);
        }

        float o[8][4];
#pragma unroll
        for (int nt = 0; nt < 8; nt++)
#pragma unroll
            for (int j = 0; j < 4; j++) o[nt][j] = 0.0f;
        float m_lo = -1e30f, m_hi = -1e30f, l_lo = 0.0f, l_hi = 0.0f;

        auto load_kv = [&](int st, int ts) {    // loads 128 tokens
#pragma unroll
            for (int it = 0; it < 4; it++) {
                int id = tid + it * 256;         // 0..1023
                int r = id >> 3, ch = id & 7;
                cp16s(kb_base + st * ABUF2 + r * AROW + ch * 16,
                      &Kb[(size_t)(ts * 128 + r) * 64 + ch * 8]);
                cp16s(vb_base + st * ABUF2 + r * AROW + ch * 16,
                      &Vb[(size_t)(ts * 128 + r) * 64 + ch * 8]);
            }
        };

        load_kv(0, 0);
        CP_COMMIT;

        for (int ts = 0; ts < n128; ts++) {
            int st = ts & 1;
            if (ts + 1 < n128) { load_kv(st ^ 1, ts + 1); CP_COMMIT; CP_WAIT1; }
            else               { CP_WAIT0; }
            __syncthreads();

#pragma unroll
            for (int sub = 0; sub < 2; sub++) {
                int kt = ts * 2 + sub;
                if (kt * 64 > row_top) break;

                unsigned kst = kb_base + st * ABUF2 + sub * 64 * AROW;
                unsigned vst = vb_base + st * ABUF2 + sub * 64 * AROW;

                float s[8][4];
#pragma unroll
                for (int nt = 0; nt < 8; nt++)
#pragma unroll
                    for (int j = 0; j < 4; j++) s[nt][j] = 0.0f;

#pragma unroll
                for (int ks = 0; ks < 4; ks++) {
#pragma unroll
                    for (int ntp = 0; ntp < 4; ntp++) {
                        int trow = ntp * 16 + (lane & 7) + ((lane >> 4) << 3);
                        unsigned addr = kst + trow * AROW + ks * 32
                                      + ((lane >> 3) & 1) * 16;
                        unsigned r[4];
                        ldsm_x4(r, addr);
                        mma_f16(s[2 * ntp],     qf[ks], r[0], r[1]);
                        mma_f16(s[2 * ntp + 1], qf[ks], r[2], r[3]);
                    }
                }

                if (kt >= qt2) {
#pragma unroll
                    for (int nt = 0; nt < 8; nt++) {
                        int key0 = kt * 64 + nt * 8 + 2 * (lane & 3);
                        if (key0     > row_lo)     s[nt][0] = -1e30f;
                        if (key0 + 1 > row_lo)     s[nt][1] = -1e30f;
                        if (key0     > row_lo + 8) s[nt][2] = -1e30f;
                        if (key0 + 1 > row_lo + 8) s[nt][3] = -1e30f;
                    }
                }

                float mloc_lo = -1e30f, mloc_hi = -1e30f;
#pragma unroll
                for (int nt = 0; nt < 8; nt++) {
                    mloc_lo = fmaxf(mloc_lo, fmaxf(s[nt][0], s[nt][1]));
                    mloc_hi = fmaxf(mloc_hi, fmaxf(s[nt][2], s[nt][3]));
                }
                mloc_lo = fmaxf(mloc_lo, __shfl_xor_sync(0xffffffffu, mloc_lo, 1));
                mloc_lo = fmaxf(mloc_lo, __shfl_xor_sync(0xffffffffu, mloc_lo, 2));
                mloc_hi = fmaxf(mloc_hi, __shfl_xor_sync(0xffffffffu, mloc_hi, 1));
                mloc_hi = fmaxf(mloc_hi, __shfl_xor_sync(0xffffffffu, mloc_hi, 2));

                float mn_lo = fmaxf(m_lo, mloc_lo);
                float mn_hi = fmaxf(m_hi, mloc_hi);
                float scl_lo = ex2(m_lo - mn_lo);
                float scl_hi = ex2(m_hi - mn_hi);
                m_lo = mn_lo; m_hi = mn_hi;

                float lloc_lo = 0.0f, lloc_hi = 0.0f;
#pragma unroll
                for (int nt = 0; nt < 8; nt++) {
                    s[nt][0] = ex2(s[nt][0] - m_lo);
                    s[nt][1] = ex2(s[nt][1] - m_lo);
                    s[nt][2] = ex2(s[nt][2] - m_hi);
                    s[nt][3] = ex2(s[nt][3] - m_hi);
                    lloc_lo += s[nt][0] + s[nt][1];
                    lloc_hi += s[nt][2] + s[nt][3];
                }
                lloc_lo += __shfl_xor_sync(0xffffffffu, lloc_lo, 1);
                lloc_lo += __shfl_xor_sync(0xffffffffu, lloc_lo, 2);
                lloc_hi += __shfl_xor_sync(0xffffffffu, lloc_hi, 1);
                lloc_hi += __shfl_xor_sync(0xffffffffu, lloc_hi, 2);
                l_lo = l_lo * scl_lo + lloc_lo;
                l_hi = l_hi * scl_hi + lloc_hi;

#pragma unroll
                for (int nt = 0; nt < 8; nt++) {
                    o[nt][0] *= scl_lo; o[nt][1] *= scl_lo;
                    o[nt][2] *= scl_hi; o[nt][3] *= scl_hi;
                }

#pragma unroll
                for (int ks = 0; ks < 4; ks++) {
                    unsigned pa[4];
                    pa[0] = packh2(s[2 * ks][0],     s[2 * ks][1]);
                    pa[1] = packh2(s[2 * ks][2],     s[2 * ks][3]);
                    pa[2] = packh2(s[2 * ks + 1][0], s[2 * ks + 1][1]);
                    pa[3] = packh2(s[2 * ks + 1][2], s[2 * ks + 1][3]);
#pragma unroll
                    for (int ntp = 0; ntp < 4; ntp++) {
                        int trow = ks * 16 + (lane & 7) + ((lane >> 3) & 1) * 8;
                        unsigned addr = vst + trow * AROW
                                      + (2 * ntp + (lane >> 4)) * 16;
                        unsigned r[4];
                        ldsm_x4_t(r, addr);
                        mma_f16(o[2 * ntp],     pa, r[0], r[1]);
                        mma_f16(o[2 * ntp + 1], pa, r[2], r[3]);
                    }
                }
            }
            __syncthreads();
        }

        float inv_lo = 1.0f / l_lo;
        float inv_hi = 1.0f / l_hi;
        size_t rb_lo = ((size_t)b * S_ + row_lo) * HID_;
        size_t rb_hi = ((size_t)b * S_ + row_lo + 8) * HID_;
#pragma unroll
        for (int nt = 0; nt < 8; nt++) {
            int col = h * 64 + nt * 8 + 2 * (lane & 3);
            *(unsigned*)&Out[rb_lo + col] =
                packh2(o[nt][0] * inv_lo, o[nt][1] * inv_lo);
            *(unsigned*)&Out[rb_hi + col] =
                packh2(o[nt][2] * inv_hi, o[nt][3] * inv_hi);
        }
    }
}

// ---------------- launch ----------------------------------------------------
extern "C" void kernel_launch(void* const* d_in, const int* in_sizes, int n_in,
                              void* d_out, int out_size) {
    const float* hidden  = (const float*)d_in[0];
    const float* w_qkv   = (const float*)d_in[1];
    const float* w_dense = (const float*)d_in[2];
    const float* b_dense = (const float*)d_in[3];
    float* out = (float*)d_out;

    void *p_attno, *p_hid, *p_wqkv, *p_wdense;
    cudaGetSymbolAddress(&p_attno, g_attno);
    cudaGetSymbolAddress(&p_hid, g_hid_h);
    cudaGetSymbolAddress(&p_wqkv, g_wqkv_t);
    cudaGetSymbolAddress(&p_wdense, g_wdense_t);

    prep_kernel<<<(PREP_N2 + 255) / 256, 256>>>(hidden);
    transpose_both_kernel<<<TTOT_BLKS, dim3(32, 8)>>>(w_qkv, w_dense);

    size_t gsmem = 4 * GBUF;   // 73728 (2 A bufs + 2 B bufs, BK=64)
    cudaFuncSetAttribute(gemm16_qkv, cudaFuncAttributeMaxDynamicSharedMemorySize,
                         (int)gsmem);
    cudaFuncSetAttribute(gemm16_dense, cudaFuncAttributeMaxDynamicSharedMemorySize,
                         (int)gsmem);

    // persistent QKV GEMM: 296 CTAs, atomic ticket over 768 tiles
    gemm16_qkv<<<296, 256, gsmem>>>((const __half*)p_hid,
                                    (const __half*)p_wqkv);

    {
        size_t asmem = 4 * ABUF2;   // 73728 (double-buffered 128-token K + V)
        cudaFuncSetAttribute(attn16, cudaFuncAttributeMaxDynamicSharedMemorySize,
                             (int)asmem);
        // persistent attention: 296 CTAs, 512 descending tickets
        attn16<<<296, 256, asmem>>>((__half*)p_attno);
    }

    {
        dim3 grid(HID_ / 128, M_ / 128);
        gemm16_dense<<<grid, 256, gsmem>>>((const __half*)p_attno,
                                           (const __half*)p_wdense, b_dense, out);
    }
}

// round 15
// speedup vs baseline: 1.0094x; 1.0094x over previous
#include <cuda_runtime.h>
#include <cuda_fp16.h>
#include <math.h>

#define B_   2
#define S_   2048
#define HID_ 1024
#define NH_  16
#define HD_  64
#define M_   (B_ * S_)        // 4096
#define QKV_N (3 * HID_)      // 3072
#define QKV_TILES (24 * 32)   // 768
#define ATTN_TICKETS 512      // 16 q-blocks x 32 bh

// ---------------- scratch (device globals) ---------------------------------
__device__ __half g_q[B_ * NH_ * S_ * HD_];    // [b,h,s,d] fp16, pre-scaled
__device__ __half g_k[B_ * NH_ * S_ * HD_];
__device__ __half g_v[B_ * NH_ * S_ * HD_];
__device__ __half g_attno[M_ * HID_];          // [b,s,hid] fp16
__device__ float  g_cos[S_ * HD_];
__device__ float  g_sin[S_ * HD_];
__device__ __half g_hid_h[M_ * HID_];          // fp16 [M,K]
__device__ __half g_wqkv_t[QKV_N * HID_];      // [N,K] fp16 (transposed)
__device__ __half g_wdense_t[HID_ * HID_];     // [N,K] fp16 (transposed)
__device__ unsigned g_qkv_ctr;                 // persistent-GEMM ticket
__device__ unsigned g_attn_ctr;                // persistent-attention ticket

// ---------------- helpers ---------------------------------------------------
__device__ __forceinline__ float ex2(float x) {
    float r;
    asm("ex2.approx.f32 %0, %1;" : "=f"(r) : "f"(x));
    return r;
}
__device__ __forceinline__ unsigned packh2(float a, float b) {
    __half2 h = __floats2half2_rn(a, b);
    return *(unsigned*)&h;
}
__device__ __forceinline__ void mma_f16(float* c, const unsigned* a,
                                        unsigned b0, unsigned b1) {
    asm volatile(
        "mma.sync.aligned.m16n8k16.row.col.f32.f16.f16.f32 "
        "{%0,%1,%2,%3}, {%4,%5,%6,%7}, {%8,%9}, {%0,%1,%2,%3};\n"
        : "+f"(c[0]), "+f"(c[1]), "+f"(c[2]), "+f"(c[3])
        : "r"(a[0]), "r"(a[1]), "r"(a[2]), "r"(a[3]), "r"(b0), "r"(b1));
}
__device__ __forceinline__ void ldsm_x4(unsigned* r, unsigned saddr) {
    asm volatile("ldmatrix.sync.aligned.m8n8.x4.shared.b16 {%0,%1,%2,%3}, [%4];"
                 : "=r"(r[0]), "=r"(r[1]), "=r"(r[2]), "=r"(r[3]) : "r"(saddr));
}
__device__ __forceinline__ void ldsm_x4_t(unsigned* r, unsigned saddr) {
    asm volatile("ldmatrix.sync.aligned.m8n8.x4.trans.shared.b16 {%0,%1,%2,%3}, [%4];"
                 : "=r"(r[0]), "=r"(r[1]), "=r"(r[2]), "=r"(r[3]) : "r"(saddr));
}
__device__ __forceinline__ void cp16s(unsigned saddr, const void* gmem) {
    asm volatile("cp.async.cg.shared.global [%0], [%1], 16;" :: "r"(saddr), "l"(gmem));
}
#define CP_COMMIT asm volatile("cp.async.commit_group;")
#define CP_WAIT0  asm volatile("cp.async.wait_group 0;")
#define CP_WAIT1  asm volatile("cp.async.wait_group 1;")

// ---------------- merged prep kernel (hidden cvt + rope + tickets) ----------
#define PREP_N1 (M_ * HID_ / 4)                  // 1048576
#define PREP_N2 (PREP_N1 + S_ * HD_)             // 1179648

__global__ void prep_kernel(const float* __restrict__ hidden) {
    int i = blockIdx.x * blockDim.x + threadIdx.x;
    if (i == 0) { g_qkv_ctr = 0; g_attn_ctr = 0; }
    if (i < PREP_N1) {
        float4 f = ((const float4*)hidden)[i];
        ((uint2*)g_hid_h)[i] = make_uint2(packh2(f.x, f.y), packh2(f.z, f.w));
    } else if (i < PREP_N2) {
        int idx = i - PREP_N1;
        int s = idx >> 6;
        int d = idx & 63;
        int k = d & 31;
        double inv = pow(10000.0, -((double)(2 * k)) / (double)HD_);
        float freq = (float)s * (float)inv;
        g_cos[idx] = (float)cos((double)freq);
        g_sin[idx] = (float)sin((double)freq);
    }
}

// ---------------- merged weight transpose ------------------------------------
#define TQKV_BLKS (96 * 32)
#define TTOT_BLKS (TQKV_BLKS + 32 * 32)

__global__ void transpose_both_kernel(const float* __restrict__ wqkv,
                                      const float* __restrict__ wdense) {
    __shared__ float t[32][33];
    int bid = blockIdx.x;
    const float* in;
    __half* out;
    int R = HID_, C;
    int bx, by;
    if (bid < TQKV_BLKS) {
        in = wqkv; out = g_wqkv_t; C = QKV_N;
        bx = bid % 96; by = bid / 96;
    } else {
        in = wdense; out = g_wdense_t; C = HID_;
        int b2 = bid - TQKV_BLKS;
        bx = b2 % 32; by = b2 / 32;
    }
    int rb = by * 32, cb = bx * 32;
    int tx = threadIdx.x, ty = threadIdx.y;
#pragma unroll
    for (int i = ty; i < 32; i += 8)
        t[i][tx] = in[(size_t)(rb + i) * C + cb + tx];
    __syncthreads();
#pragma unroll
    for (int i = ty; i < 32; i += 8)
        out[(size_t)(cb + i) * R + rb + tx] = __float2half_rn(t[tx][i]);
}

// ---------------- fp16 GEMM mainloop (BK=64, double-buffered) ----------------
#define GROW 144                    // bytes per smem row (64 halfs + 16B pad)
#define GBUF (128 * GROW)           // 18432 bytes per tile buffer

__device__ __forceinline__ void gemm16_main(
    const __half* __restrict__ A, const __half* __restrict__ Wt,
    int row0, int col0, unsigned smem_base, float acc[2][8][4],
    int tid, int lane, int wm, int wn)
{
#pragma unroll
    for (int mt = 0; mt < 2; mt++)
#pragma unroll
        for (int nt = 0; nt < 8; nt++)
#pragma unroll
            for (int j = 0; j < 4; j++) acc[mt][nt][j] = 0.0f;

    auto load_tile = [&](int st, int t) {
        int k0 = t * 64;
        unsigned sa = smem_base + st * GBUF;
        unsigned sb = smem_base + 2 * GBUF + st * GBUF;
#pragma unroll
        for (int it = 0; it < 4; it++) {
            int id = tid + it * 256;          // 0..1023
            int r = id >> 3, ch = id & 7;
            cp16s(sa + r * GROW + ch * 16,
                  &A[(size_t)(row0 + r) * HID_ + k0 + ch * 8]);
        }
#pragma unroll
        for (int it = 0; it < 4; it++) {
            int id = tid + it * 256;
            int r = id >> 3, ch = id & 7;
            cp16s(sb + r * GROW + ch * 16,
                  &Wt[(size_t)(col0 + r) * HID_ + k0 + ch * 8]);
        }
    };

    load_tile(0, 0); CP_COMMIT;

    for (int t = 0; t < 16; t++) {
        int st = t & 1;
        if (t + 1 < 16) { load_tile(st ^ 1, t + 1); CP_COMMIT; CP_WAIT1; }
        else            { CP_WAIT0; }
        __syncthreads();

        unsigned sa = smem_base + st * GBUF;
        unsigned sb = smem_base + 2 * GBUF + st * GBUF;
#pragma unroll
        for (int ks = 0; ks < 4; ks++) {
            unsigned a[2][4];
#pragma unroll
            for (int mt = 0; mt < 2; mt++) {
                unsigned addr = sa + (wm + mt * 16 + (lane & 15)) * GROW
                              + ks * 32 + (lane >> 4) * 16;
                ldsm_x4(a[mt], addr);
            }
            unsigned b[8][2];
#pragma unroll
            for (int ntp = 0; ntp < 4; ntp++) {
                int nrow = wn + ntp * 16 + (lane & 7) + ((lane >> 4) << 3);
                unsigned addr = sb + nrow * GROW + ks * 32 + ((lane >> 3) & 1) * 16;
                unsigned r[4];
                ldsm_x4(r, addr);
                b[2 * ntp][0]     = r[0]; b[2 * ntp][1]     = r[1];
                b[2 * ntp + 1][0] = r[2]; b[2 * ntp + 1][1] = r[3];
            }
#pragma unroll
            for (int mt = 0; mt < 2; mt++)
#pragma unroll
                for (int nt = 0; nt < 8; nt++)
                    mma_f16(acc[mt][nt], a[mt], b[nt][0], b[nt][1]);
        }
        __syncthreads();
    }
}

// ---------------- QKV GEMM (persistent) + fused RoPE/split epilogue ---------
__global__ __launch_bounds__(256, 2)
void gemm16_qkv(const __half* __restrict__ A, const __half* __restrict__ Wt) {
    extern __shared__ char dsm[];
    __shared__ int s_tile;
    unsigned smem_base = (unsigned)__cvta_generic_to_shared(dsm);
    int tid = threadIdx.x, lane = tid & 31, warp = tid >> 5;
    int wm = (warp & 3) * 32;
    int wn = (warp >> 2) * 64;
    const float QS = 0.125f * 1.4426950408889634f;

    for (;;) {
        if (tid == 0) s_tile = (int)atomicAdd(&g_qkv_ctr, 1u);
        __syncthreads();
        int t = s_tile;
        if (t >= QKV_TILES) break;
        int row0 = (t & 31) * 128;
        int col0 = (t >> 5) * 128;

        float acc[2][8][4];
        gemm16_main(A, Wt, row0, col0, smem_base, acc, tid, lane, wm, wn);

        int region = col0 >> 10;                 // 0=q 1=k 2=v
        int h      = ((col0 & 1023) + wn) >> 6;  // warp covers one head

#pragma unroll
        for (int mt = 0; mt < 2; mt++) {
            int r = row0 + wm + mt * 16 + (lane >> 2);
            int b = r >> 11, s = r & 2047;
            size_t base_lo = ((size_t)((b << 4) + h) * S_ + s) * 64;
            size_t base_hi = base_lo + 8 * 64;

            if (region == 2) {
#pragma unroll
                for (int nt = 0; nt < 8; nt++) {
                    int d = nt * 8 + 2 * (lane & 3);
                    *(unsigned*)&g_v[base_lo + d] =
                        packh2(acc[mt][nt][0], acc[mt][nt][1]);
                    *(unsigned*)&g_v[base_hi + d] =
                        packh2(acc[mt][nt][2], acc[mt][nt][3]);
                }
            } else {
                __half* dst = (region == 0) ? g_q : g_k;
                float SC    = (region == 0) ? QS : 1.0f;
#pragma unroll
                for (int nt = 0; nt < 4; nt++) {
                    int d = nt * 8 + 2 * (lane & 3);    // d < 32
                    float2 cl = *(const float2*)&g_cos[s * 64 + d];
                    float2 sl = *(const float2*)&g_sin[s * 64 + d];
                    float2 ch = *(const float2*)&g_cos[(s + 8) * 64 + d];
                    float2 sh = *(const float2*)&g_sin[(s + 8) * 64 + d];

                    float x0 = acc[mt][nt][0],     x1 = acc[mt][nt][1];
                    float x2 = acc[mt][nt][2],     x3 = acc[mt][nt][3];
                    float y0 = acc[mt][nt + 4][0], y1 = acc[mt][nt + 4][1];
                    float y2 = acc[mt][nt + 4][2], y3 = acc[mt][nt + 4][3];

                    *(unsigned*)&dst[base_lo + d] =
                        packh2((x0 * cl.x - y0 * sl.x) * SC,
                               (x1 * cl.y - y1 * sl.y) * SC);
                    *(unsigned*)&dst[base_lo + d + 32] =
                        packh2((y0 * cl.x + x0 * sl.x) * SC,
                               (y1 * cl.y + x1 * sl.y) * SC);
                    *(unsigned*)&dst[base_hi + d] =
                        packh2((x2 * ch.x - y2 * sh.x) * SC,
                               (x3 * ch.y - y3 * sh.y) * SC);
                    *(unsigned*)&dst[base_hi + d + 32] =
                        packh2((y2 * ch.x + x2 * sh.x) * SC,
                               (y3 * ch.y + x3 * sh.y) * SC);
                }
            }
        }
    }
}

// ---------------- dense GEMM + bias (fp32 out) -------------------------------
__global__ __launch_bounds__(256, 2)
void gemm16_dense(const __half* __restrict__ A, const __half* __restrict__ Wt,
                  const float* __restrict__ bias, float* __restrict__ C) {
    extern __shared__ char dsm[];
    unsigned smem_base = (unsigned)__cvta_generic_to_shared(dsm);
    int tid = threadIdx.x, lane = tid & 31, warp = tid >> 5;
    int row0 = blockIdx.y * 128;
    int col0 = blockIdx.x * 128;
    int wm = (warp & 3) * 32;
    int wn = (warp >> 2) * 64;

    float acc[2][8][4];
    gemm16_main(A, Wt, row0, col0, smem_base, acc, tid, lane, wm, wn);

#pragma unroll
    for (int mt = 0; mt < 2; mt++) {
        int r = row0 + wm + mt * 16 + (lane >> 2);
#pragma unroll
        for (int nt = 0; nt < 8; nt++) {
            int c = col0 + wn + nt * 8 + 2 * (lane & 3);
            float bx = bias[c], by = bias[c + 1];
            float2 lo, hi;
            lo.x = acc[mt][nt][0] + bx; lo.y = acc[mt][nt][1] + by;
            hi.x = acc[mt][nt][2] + bx; hi.y = acc[mt][nt][3] + by;
            *(float2*)&C[(size_t)r * HID_ + c]       = lo;
            *(float2*)&C[(size_t)(r + 8) * HID_ + c] = hi;
        }
    }
}

// ---------------- causal flash attention (persistent, ticketed) --------------
// 296 CTAs; 512 tickets, heaviest q-blocks first: qblk = 15 - tk/32, bh = tk%32.
#define AROW 144
#define ABUF (64 * AROW)            // 9216

__global__ __launch_bounds__(256, 2)
void attn16(__half* __restrict__ Out) {
    extern __shared__ char dsm[];
    __shared__ int s_tk;
    unsigned smem_base = (unsigned)__cvta_generic_to_shared(dsm);
    unsigned kb_base = smem_base;               // K: [2][ABUF]
    unsigned vb_base = smem_base + 2 * ABUF;    // V: [2][ABUF]

    int tid  = threadIdx.x;
    int lane = tid & 31;
    int warp = tid >> 5;

    for (;;) {
        if (tid == 0) s_tk = (int)atomicAdd(&g_attn_ctr, 1u);
        __syncthreads();
        int tk = s_tk;
        if (tk >= ATTN_TICKETS) break;
        int qblk = 15 - (tk >> 5);              // heaviest first
        int bh   = tk & 31;
        int b = bh >> 4, h = bh & 15;

        const __half* Qb = g_q + (size_t)bh * S_ * HD_;
        const __half* Kb = g_k + (size_t)bh * S_ * HD_;
        const __half* Vb = g_v + (size_t)bh * S_ * HD_;

        int qb   = qblk * 128;
        int qt2  = qblk * 2;
        int nkt  = qt2 + 2;
        int row_lo = qb + warp * 16 + (lane >> 2);

        unsigned qf[4][4];
#pragma unroll
        for (int ks = 0; ks < 4; ks++) {
            const __half* qp = Qb + (size_t)row_lo * 64 + ks * 16 + 2 * (lane & 3);
            qf[ks][0] = *(const unsigned*)(qp);
            qf[ks][1] = *(const unsigned*)(qp + 8 * 64);
            qf[ks][2] = *(const unsigned*)(qp + 8);
            qf[ks][3] = *(const unsigned*)(qp + 8 * 64 + 8);
        }

        float o[8][4];
#pragma unroll
        for (int nt = 0; nt < 8; nt++)
#pragma unroll
            for (int j = 0; j < 4; j++) o[nt][j] = 0.0f;
        float m_lo = -1e30f, m_hi = -1e30f, l_lo = 0.0f, l_hi = 0.0f;

        auto load_kv = [&](int st, int kt) {
#pragma unroll
            for (int it = 0; it < 2; it++) {
                int id = tid + it * 256;
                int r = id >> 3, ch = id & 7;
                cp16s(kb_base + st * ABUF + r * AROW + ch * 16,
                      &Kb[(size_t)(kt * 64 + r) * 64 + ch * 8]);
                cp16s(vb_base + st * ABUF + r * AROW + ch * 16,
                      &Vb[(size_t)(kt * 64 + r) * 64 + ch * 8]);
            }
        };

        load_kv(0, 0);
        CP_COMMIT;

        for (int kt = 0; kt < nkt; kt++) {
            int st = kt & 1;
            if (kt + 1 < nkt) { load_kv(st ^ 1, kt + 1); CP_COMMIT; CP_WAIT1; }
            else              { CP_WAIT0; }
            __syncthreads();

            if (kt * 64 <= qb + warp * 16 + 15) {
                unsigned kst = kb_base + st * ABUF;
                unsigned vst = vb_base + st * ABUF;

                float s[8][4];
#pragma unroll
                for (int nt = 0; nt < 8; nt++)
#pragma unroll
                    for (int j = 0; j < 4; j++) s[nt][j] = 0.0f;

#pragma unroll
                for (int ks = 0; ks < 4; ks++) {
#pragma unroll
                    for (int ntp = 0; ntp < 4; ntp++) {
                        int trow = ntp * 16 + (lane & 7) + ((lane >> 4) << 3);
                        unsigned addr = kst + trow * AROW + ks * 32
                                      + ((lane >> 3) & 1) * 16;
                        unsigned r[4];
                        ldsm_x4(r, addr);
                        mma_f16(s[2 * ntp],     qf[ks], r[0], r[1]);
                        mma_f16(s[2 * ntp + 1], qf[ks], r[2], r[3]);
                    }
                }

                if (kt >= qt2) {
#pragma unroll
                    for (int nt = 0; nt < 8; nt++) {
                        int key0 = kt * 64 + nt * 8 + 2 * (lane & 3);
                        if (key0     > row_lo)     s[nt][0] = -1e30f;
                        if (key0 + 1 > row_lo)     s[nt][1] = -1e30f;
                        if (key0     > row_lo + 8) s[nt][2] = -1e30f;
                        if (key0 + 1 > row_lo + 8) s[nt][3] = -1e30f;
                    }
                }

                float mloc_lo = -1e30f, mloc_hi = -1e30f;
#pragma unroll
                for (int nt = 0; nt < 8; nt++) {
                    mloc_lo = fmaxf(mloc_lo, fmaxf(s[nt][0], s[nt][1]));
                    mloc_hi = fmaxf(mloc_hi, fmaxf(s[nt][2], s[nt][3]));
                }
                mloc_lo = fmaxf(mloc_lo, __shfl_xor_sync(0xffffffffu, mloc_lo, 1));
                mloc_lo = fmaxf(mloc_lo, __shfl_xor_sync(0xffffffffu, mloc_lo, 2));
                mloc_hi = fmaxf(mloc_hi, __shfl_xor_sync(0xffffffffu, mloc_hi, 1));
                mloc_hi = fmaxf(mloc_hi, __shfl_xor_sync(0xffffffffu, mloc_hi, 2));

                float mn_lo = fmaxf(m_lo, mloc_lo);
                float mn_hi = fmaxf(m_hi, mloc_hi);
                float scl_lo = ex2(m_lo - mn_lo);
                float scl_hi = ex2(m_hi - mn_hi);
                m_lo = mn_lo; m_hi = mn_hi;

                float lloc_lo = 0.0f, lloc_hi = 0.0f;
#pragma unroll
                for (int nt = 0; nt < 8; nt++) {
                    s[nt][0] = ex2(s[nt][0] - m_lo);
                    s[nt][1] = ex2(s[nt][1] - m_lo);
                    s[nt][2] = ex2(s[nt][2] - m_hi);
                    s[nt][3] = ex2(s[nt][3] - m_hi);
                    lloc_lo += s[nt][0] + s[nt][1];
                    lloc_hi += s[nt][2] + s[nt][3];
                }
                lloc_lo += __shfl_xor_sync(0xffffffffu, lloc_lo, 1);
                lloc_lo += __shfl_xor_sync(0xffffffffu, lloc_lo, 2);
                lloc_hi += __shfl_xor_sync(0xffffffffu, lloc_hi, 1);
                lloc_hi += __shfl_xor_sync(0xffffffffu, lloc_hi, 2);
                l_lo = l_lo * scl_lo + lloc_lo;
                l_hi = l_hi * scl_hi + lloc_hi;

#pragma unroll
                for (int nt = 0; nt < 8; nt++) {
                    o[nt][0] *= scl_lo; o[nt][1] *= scl_lo;
                    o[nt][2] *= scl_hi; o[nt][3] *= scl_hi;
                }

#pragma unroll
                for (int ks = 0; ks < 4; ks++) {
                    unsigned pa[4];
                    pa[0] = packh2(s[2 * ks][0],     s[2 * ks][1]);
                    pa[1] = packh2(s[2 * ks][2],     s[2 * ks][3]);
                    pa[2] = packh2(s[2 * ks + 1][0], s[2 * ks + 1][1]);
                    pa[3] = packh2(s[2 * ks + 1][2], s[2 * ks + 1][3]);
#pragma unroll
                    for (int ntp = 0; ntp < 4; ntp++) {
                        int trow = ks * 16 + (lane & 7) + ((lane >> 3) & 1) * 8;
                        unsigned addr = vst + trow * AROW
                                      + (2 * ntp + (lane >> 4)) * 16;
                        unsigned r[4];
                        ldsm_x4_t(r, addr);
                        mma_f16(o[2 * ntp],     pa, r[0], r[1]);
                        mma_f16(o[2 * ntp + 1], pa, r[2], r[3]);
                    }
                }
            }
            __syncthreads();
        }

        float inv_lo = 1.0f / l_lo;
        float inv_hi = 1.0f / l_hi;
        size_t rb_lo = ((size_t)b * S_ + row_lo) * HID_;
        size_t rb_hi = ((size_t)b * S_ + row_lo + 8) * HID_;
#pragma unroll
        for (int nt = 0; nt < 8; nt++) {
            int col = h * 64 + nt * 8 + 2 * (lane & 3);
            *(unsigned*)&Out[rb_lo + col] =
                packh2(o[nt][0] * inv_lo, o[nt][1] * inv_lo);
            *(unsigned*)&Out[rb_hi + col] =
                packh2(o[nt][2] * inv_hi, o[nt][3] * inv_hi);
        }
    }
}

// ---------------- launch ----------------------------------------------------
extern "C" void kernel_launch(void* const* d_in, const int* in_sizes, int n_in,
                              void* d_out, int out_size) {
    const float* hidden  = (const float*)d_in[0];
    const float* w_qkv   = (const float*)d_in[1];
    const float* w_dense = (const float*)d_in[2];
    const float* b_dense = (const float*)d_in[3];
    float* out = (float*)d_out;

    void *p_attno, *p_hid, *p_wqkv, *p_wdense;
    cudaGetSymbolAddress(&p_attno, g_attno);
    cudaGetSymbolAddress(&p_hid, g_hid_h);
    cudaGetSymbolAddress(&p_wqkv, g_wqkv_t);
    cudaGetSymbolAddress(&p_wdense, g_wdense_t);

    prep_kernel<<<(PREP_N2 + 255) / 256, 256>>>(hidden);
    transpose_both_kernel<<<TTOT_BLKS, dim3(32, 8)>>>(w_qkv, w_dense);

    size_t gsmem = 4 * GBUF;   // 73728 (2 A bufs + 2 B bufs, BK=64)
    cudaFuncSetAttribute(gemm16_qkv, cudaFuncAttributeMaxDynamicSharedMemorySize,
                         (int)gsmem);
    cudaFuncSetAttribute(gemm16_dense, cudaFuncAttributeMaxDynamicSharedMemorySize,
                         (int)gsmem);

    // persistent QKV GEMM: 296 CTAs, atomic ticket over 768 tiles
    gemm16_qkv<<<296, 256, gsmem>>>((const __half*)p_hid,
                                    (const __half*)p_wqkv);

    {
        size_t asmem = 4 * ABUF;   // 36864 (double-buffered K + V)
        cudaFuncSetAttribute(attn16, cudaFuncAttributeMaxDynamicSharedMemorySize,
                             (int)asmem);
        // persistent attention: 296 CTAs, 512 descending tickets
        attn16<<<296, 256, asmem>>>((__half*)p_attno);
    }

    {
        dim3 grid(HID_ / 128, M_ / 128);
        gemm16_dense<<<grid, 256, gsmem>>>((const __half*)p_attno,
                                           (const __half*)p_wdense, b_dense, out);
    }
}

// round 16
// speedup vs baseline: 1.0584x; 1.0485x over previous
#include <cuda_runtime.h>
#include <cuda_fp16.h>
#include <math.h>

#define B_   2
#define S_   2048
#define HID_ 1024
#define NH_  16
#define HD_  64
#define M_   (B_ * S_)        // 4096
#define QKV_N (3 * HID_)      // 3072
#define QKV_TILES (24 * 32)   // 768
#define ATTN_TICKETS 512      // 16 q-blocks x 32 bh

// ---------------- scratch (device globals) ---------------------------------
__device__ __half g_q[B_ * NH_ * S_ * HD_];    // [b,h,s,d] fp16, pre-scaled
__device__ __half g_k[B_ * NH_ * S_ * HD_];
__device__ __half g_v[B_ * NH_ * S_ * HD_];
__device__ __half g_attno[M_ * HID_];          // [b,s,hid] fp16
__device__ float  g_cos[S_ * HD_];
__device__ float  g_sin[S_ * HD_];
__device__ __half g_hid_h[M_ * HID_];          // fp16 [M,K]
__device__ __half g_wqkv_t[QKV_N * HID_];      // [N,K] fp16 (transposed)
__device__ __half g_wdense_t[HID_ * HID_];     // [N,K] fp16 (transposed)
__device__ unsigned g_qkv_ctr;                 // persistent-GEMM ticket
__device__ unsigned g_attn_ctr;                // persistent-attention ticket

// ---------------- helpers ---------------------------------------------------
__device__ __forceinline__ float ex2(float x) {
    float r;
    asm("ex2.approx.f32 %0, %1;" : "=f"(r) : "f"(x));
    return r;
}
__device__ __forceinline__ unsigned packh2(float a, float b) {
    __half2 h = __floats2half2_rn(a, b);
    return *(unsigned*)&h;
}
__device__ __forceinline__ void mma_f16(float* c, const unsigned* a,
                                        unsigned b0, unsigned b1) {
    asm volatile(
        "mma.sync.aligned.m16n8k16.row.col.f32.f16.f16.f32 "
        "{%0,%1,%2,%3}, {%4,%5,%6,%7}, {%8,%9}, {%0,%1,%2,%3};\n"
        : "+f"(c[0]), "+f"(c[1]), "+f"(c[2]), "+f"(c[3])
        : "r"(a[0]), "r"(a[1]), "r"(a[2]), "r"(a[3]), "r"(b0), "r"(b1));
}
__device__ __forceinline__ void ldsm_x4(unsigned* r, unsigned saddr) {
    asm volatile("ldmatrix.sync.aligned.m8n8.x4.shared.b16 {%0,%1,%2,%3}, [%4];"
                 : "=r"(r[0]), "=r"(r[1]), "=r"(r[2]), "=r"(r[3]) : "r"(saddr));
}
__device__ __forceinline__ void ldsm_x4_t(unsigned* r, unsigned saddr) {
    asm volatile("ldmatrix.sync.aligned.m8n8.x4.trans.shared.b16 {%0,%1,%2,%3}, [%4];"
                 : "=r"(r[0]), "=r"(r[1]), "=r"(r[2]), "=r"(r[3]) : "r"(saddr));
}
__device__ __forceinline__ void cp16s(unsigned saddr, const void* gmem) {
    asm volatile("cp.async.cg.shared.global [%0], [%1], 16;" :: "r"(saddr), "l"(gmem));
}
#define CP_COMMIT asm volatile("cp.async.commit_group;")
#define CP_WAIT0  asm volatile("cp.async.wait_group 0;")
#define CP_WAIT1  asm volatile("cp.async.wait_group 1;")

// ---------------- merged prep+transpose kernel -------------------------------
// blocks [0, PREP_BLKS): hidden f32->f16 cvt + rope table + ticket reset
// blocks [PREP_BLKS, PREP_BLKS+TQKV_BLKS): w_qkv transpose
// blocks [.., +TDEN_BLKS): w_dense transpose
#define PREP_N1 (M_ * HID_ / 4)                  // 1048576
#define PREP_N2 (PREP_N1 + S_ * HD_)             // 1179648
#define PREP_BLKS ((PREP_N2 + 255) / 256)        // 4608
#define TQKV_BLKS (96 * 32)                      // 3072
#define TDEN_BLKS (32 * 32)                      // 1024
#define ALL_BLKS  (PREP_BLKS + TQKV_BLKS + TDEN_BLKS)

__global__ void prep_all_kernel(const float* __restrict__ hidden,
                                const float* __restrict__ wqkv,
                                const float* __restrict__ wdense) {
    int bid = blockIdx.x;
    if (bid < PREP_BLKS) {
        int i = bid * 256 + threadIdx.x;
        if (i == 0) { g_qkv_ctr = 0; g_attn_ctr = 0; }
        if (i < PREP_N1) {
            float4 f = ((const float4*)hidden)[i];
            ((uint2*)g_hid_h)[i] = make_uint2(packh2(f.x, f.y), packh2(f.z, f.w));
        } else if (i < PREP_N2) {
            int idx = i - PREP_N1;
            int s = idx >> 6;
            int d = idx & 63;
            int k = d & 31;
            double inv = pow(10000.0, -((double)(2 * k)) / (double)HD_);
            float freq = (float)s * (float)inv;
            g_cos[idx] = (float)cos((double)freq);
            g_sin[idx] = (float)sin((double)freq);
        }
        return;
    }
    // transpose region: remap 256 threads -> 32x8
    __shared__ float t[32][33];
    int tb = bid - PREP_BLKS;
    const float* in;
    __half* out;
    int R = HID_, C;
    int bx, by;
    if (tb < TQKV_BLKS) {
        in = wqkv; out = g_wqkv_t; C = QKV_N;
        bx = tb % 96; by = tb / 96;
    } else {
        in = wdense; out = g_wdense_t; C = HID_;
        int b2 = tb - TQKV_BLKS;
        bx = b2 % 32; by = b2 / 32;
    }
    int rb = by * 32, cb = bx * 32;
    int tx = threadIdx.x & 31, ty = threadIdx.x >> 5;
#pragma unroll
    for (int i = ty; i < 32; i += 8)
        t[i][tx] = in[(size_t)(rb + i) * C + cb + tx];
    __syncthreads();
#pragma unroll
    for (int i = ty; i < 32; i += 8)
        out[(size_t)(cb + i) * R + rb + tx] = __float2half_rn(t[tx][i]);
}

// ---------------- fp16 GEMM mainloop (BK=64, double-buffered) ----------------
#define GROW 144                    // bytes per smem row (64 halfs + 16B pad)
#define GBUF (128 * GROW)           // 18432 bytes per tile buffer

__device__ __forceinline__ void gemm16_main(
    const __half* __restrict__ A, const __half* __restrict__ Wt,
    int row0, int col0, unsigned smem_base, float acc[2][8][4],
    int tid, int lane, int wm, int wn)
{
#pragma unroll
    for (int mt = 0; mt < 2; mt++)
#pragma unroll
        for (int nt = 0; nt < 8; nt++)
#pragma unroll
            for (int j = 0; j < 4; j++) acc[mt][nt][j] = 0.0f;

    auto load_tile = [&](int st, int t) {
        int k0 = t * 64;
        unsigned sa = smem_base + st * GBUF;
        unsigned sb = smem_base + 2 * GBUF + st * GBUF;
#pragma unroll
        for (int it = 0; it < 4; it++) {
            int id = tid + it * 256;          // 0..1023
            int r = id >> 3, ch = id & 7;
            cp16s(sa + r * GROW + ch * 16,
                  &A[(size_t)(row0 + r) * HID_ + k0 + ch * 8]);
        }
#pragma unroll
        for (int it = 0; it < 4; it++) {
            int id = tid + it * 256;
            int r = id >> 3, ch = id & 7;
            cp16s(sb + r * GROW + ch * 16,
                  &Wt[(size_t)(col0 + r) * HID_ + k0 + ch * 8]);
        }
    };

    load_tile(0, 0); CP_COMMIT;

    for (int t = 0; t < 16; t++) {
        int st = t & 1;
        if (t + 1 < 16) { load_tile(st ^ 1, t + 1); CP_COMMIT; CP_WAIT1; }
        else            { CP_WAIT0; }
        __syncthreads();

        unsigned sa = smem_base + st * GBUF;
        unsigned sb = smem_base + 2 * GBUF + st * GBUF;
#pragma unroll
        for (int ks = 0; ks < 4; ks++) {
            unsigned a[2][4];
#pragma unroll
            for (int mt = 0; mt < 2; mt++) {
                unsigned addr = sa + (wm + mt * 16 + (lane & 15)) * GROW
                              + ks * 32 + (lane >> 4) * 16;
                ldsm_x4(a[mt], addr);
            }
            unsigned b[8][2];
#pragma unroll
            for (int ntp = 0; ntp < 4; ntp++) {
                int nrow = wn + ntp * 16 + (lane & 7) + ((lane >> 4) << 3);
                unsigned addr = sb + nrow * GROW + ks * 32 + ((lane >> 3) & 1) * 16;
                unsigned r[4];
                ldsm_x4(r, addr);
                b[2 * ntp][0]     = r[0]; b[2 * ntp][1]     = r[1];
                b[2 * ntp + 1][0] = r[2]; b[2 * ntp + 1][1] = r[3];
            }
#pragma unroll
            for (int mt = 0; mt < 2; mt++)
#pragma unroll
                for (int nt = 0; nt < 8; nt++)
                    mma_f16(acc[mt][nt], a[mt], b[nt][0], b[nt][1]);
        }
        __syncthreads();
    }
}

// ---------------- QKV GEMM (persistent) + fused RoPE/split epilogue ---------
__global__ __launch_bounds__(256, 2)
void gemm16_qkv(const __half* __restrict__ A, const __half* __restrict__ Wt) {
    extern __shared__ char dsm[];
    __shared__ int s_tile;
    unsigned smem_base = (unsigned)__cvta_generic_to_shared(dsm);
    int tid = threadIdx.x, lane = tid & 31, warp = tid >> 5;
    int wm = (warp & 3) * 32;
    int wn = (warp >> 2) * 64;
    const float QS = 0.125f * 1.4426950408889634f;

    for (;;) {
        if (tid == 0) s_tile = (int)atomicAdd(&g_qkv_ctr, 1u);
        __syncthreads();
        int t = s_tile;
        if (t >= QKV_TILES) break;
        int row0 = (t & 31) * 128;
        int col0 = (t >> 5) * 128;

        float acc[2][8][4];
        gemm16_main(A, Wt, row0, col0, smem_base, acc, tid, lane, wm, wn);

        int region = col0 >> 10;                 // 0=q 1=k 2=v
        int h      = ((col0 & 1023) + wn) >> 6;  // warp covers one head

#pragma unroll
        for (int mt = 0; mt < 2; mt++) {
            int r = row0 + wm + mt * 16 + (lane >> 2);
            int b = r >> 11, s = r & 2047;
            size_t base_lo = ((size_t)((b << 4) + h) * S_ + s) * 64;
            size_t base_hi = base_lo + 8 * 64;

            if (region == 2) {
#pragma unroll
                for (int nt = 0; nt < 8; nt++) {
                    int d = nt * 8 + 2 * (lane & 3);
                    *(unsigned*)&g_v[base_lo + d] =
                        packh2(acc[mt][nt][0], acc[mt][nt][1]);
                    *(unsigned*)&g_v[base_hi + d] =
                        packh2(acc[mt][nt][2], acc[mt][nt][3]);
                }
            } else {
                __half* dst = (region == 0) ? g_q : g_k;
                float SC    = (region == 0) ? QS : 1.0f;
#pragma unroll
                for (int nt = 0; nt < 4; nt++) {
                    int d = nt * 8 + 2 * (lane & 3);    // d < 32
                    float2 cl = *(const float2*)&g_cos[s * 64 + d];
                    float2 sl = *(const float2*)&g_sin[s * 64 + d];
                    float2 ch = *(const float2*)&g_cos[(s + 8) * 64 + d];
                    float2 sh = *(const float2*)&g_sin[(s + 8) * 64 + d];

                    float x0 = acc[mt][nt][0],     x1 = acc[mt][nt][1];
                    float x2 = acc[mt][nt][2],     x3 = acc[mt][nt][3];
                    float y0 = acc[mt][nt + 4][0], y1 = acc[mt][nt + 4][1];
                    float y2 = acc[mt][nt + 4][2], y3 = acc[mt][nt + 4][3];

                    *(unsigned*)&dst[base_lo + d] =
                        packh2((x0 * cl.x - y0 * sl.x) * SC,
                               (x1 * cl.y - y1 * sl.y) * SC);
                    *(unsigned*)&dst[base_lo + d + 32] =
                        packh2((y0 * cl.x + x0 * sl.x) * SC,
                               (y1 * cl.y + x1 * sl.y) * SC);
                    *(unsigned*)&dst[base_hi + d] =
                        packh2((x2 * ch.x - y2 * sh.x) * SC,
                               (x3 * ch.y - y3 * sh.y) * SC);
                    *(unsigned*)&dst[base_hi + d + 32] =
                        packh2((y2 * ch.x + x2 * sh.x) * SC,
                               (y3 * ch.y + x3 * sh.y) * SC);
                }
            }
        }
    }
}

// ---------------- dense GEMM + bias (fp32 out) -------------------------------
__global__ __launch_bounds__(256, 2)
void gemm16_dense(const __half* __restrict__ A, const __half* __restrict__ Wt,
                  const float* __restrict__ bias, float* __restrict__ C) {
    extern __shared__ char dsm[];
    unsigned smem_base = (unsigned)__cvta_generic_to_shared(dsm);
    int tid = threadIdx.x, lane = tid & 31, warp = tid >> 5;
    int row0 = blockIdx.y * 128;
    int col0 = blockIdx.x * 128;
    int wm = (warp & 3) * 32;
    int wn = (warp >> 2) * 64;

    float acc[2][8][4];
    gemm16_main(A, Wt, row0, col0, smem_base, acc, tid, lane, wm, wn);

#pragma unroll
    for (int mt = 0; mt < 2; mt++) {
        int r = row0 + wm + mt * 16 + (lane >> 2);
#pragma unroll
        for (int nt = 0; nt < 8; nt++) {
            int c = col0 + wn + nt * 8 + 2 * (lane & 3);
            float bx = bias[c], by = bias[c + 1];
            float2 lo, hi;
            lo.x = acc[mt][nt][0] + bx; lo.y = acc[mt][nt][1] + by;
            hi.x = acc[mt][nt][2] + bx; hi.y = acc[mt][nt][3] + by;
            *(float2*)&C[(size_t)r * HID_ + c]       = lo;
            *(float2*)&C[(size_t)(r + 8) * HID_ + c] = hi;
        }
    }
}

// ---------------- causal flash attention (persistent, ticketed) --------------
// 296 CTAs; 512 tickets, heaviest q-blocks first: qblk = 15 - tk/32, bh = tk%32.
#define AROW 144
#define ABUF (64 * AROW)            // 9216

__global__ __launch_bounds__(256, 2)
void attn16(__half* __restrict__ Out) {
    extern __shared__ char dsm[];
    __shared__ int s_tk;
    unsigned smem_base = (unsigned)__cvta_generic_to_shared(dsm);
    unsigned kb_base = smem_base;               // K: [2][ABUF]
    unsigned vb_base = smem_base + 2 * ABUF;    // V: [2][ABUF]

    int tid  = threadIdx.x;
    int lane = tid & 31;
    int warp = tid >> 5;

    for (;;) {
        if (tid == 0) s_tk = (int)atomicAdd(&g_attn_ctr, 1u);
        __syncthreads();
        int tk = s_tk;
        if (tk >= ATTN_TICKETS) break;
        int qblk = 15 - (tk >> 5);              // heaviest first
        int bh   = tk & 31;
        int b = bh >> 4, h = bh & 15;

        const __half* Qb = g_q + (size_t)bh * S_ * HD_;
        const __half* Kb = g_k + (size_t)bh * S_ * HD_;
        const __half* Vb = g_v + (size_t)bh * S_ * HD_;

        int qb   = qblk * 128;
        int qt2  = qblk * 2;
        int nkt  = qt2 + 2;
        int row_lo = qb + warp * 16 + (lane >> 2);

        unsigned qf[4][4];
#pragma unroll
        for (int ks = 0; ks < 4; ks++) {
            const __half* qp = Qb + (size_t)row_lo * 64 + ks * 16 + 2 * (lane & 3);
            qf[ks][0] = *(const unsigned*)(qp);
            qf[ks][1] = *(const unsigned*)(qp + 8 * 64);
            qf[ks][2] = *(const unsigned*)(qp + 8);
            qf[ks][3] = *(const unsigned*)(qp + 8 * 64 + 8);
        }

        float o[8][4];
#pragma unroll
        for (int nt = 0; nt < 8; nt++)
#pragma unroll
            for (int j = 0; j < 4; j++) o[nt][j] = 0.0f;
        float m_lo = -1e30f, m_hi = -1e30f, l_lo = 0.0f, l_hi = 0.0f;

        auto load_kv = [&](int st, int kt) {
#pragma unroll
            for (int it = 0; it < 2; it++) {
                int id = tid + it * 256;
                int r = id >> 3, ch = id & 7;
                cp16s(kb_base + st * ABUF + r * AROW + ch * 16,
                      &Kb[(size_t)(kt * 64 + r) * 64 + ch * 8]);
                cp16s(vb_base + st * ABUF + r * AROW + ch * 16,
                      &Vb[(size_t)(kt * 64 + r) * 64 + ch * 8]);
            }
        };

        load_kv(0, 0);
        CP_COMMIT;

        for (int kt = 0; kt < nkt; kt++) {
            int st = kt & 1;
            if (kt + 1 < nkt) { load_kv(st ^ 1, kt + 1); CP_COMMIT; CP_WAIT1; }
            else              { CP_WAIT0; }
            __syncthreads();

            if (kt * 64 <= qb + warp * 16 + 15) {
                unsigned kst = kb_base + st * ABUF;
                unsigned vst = vb_base + st * ABUF;

                float s[8][4];
#pragma unroll
                for (int nt = 0; nt < 8; nt++)
#pragma unroll
                    for (int j = 0; j < 4; j++) s[nt][j] = 0.0f;

#pragma unroll
                for (int ks = 0; ks < 4; ks++) {
#pragma unroll
                    for (int ntp = 0; ntp < 4; ntp++) {
                        int trow = ntp * 16 + (lane & 7) + ((lane >> 4) << 3);
                        unsigned addr = kst + trow * AROW + ks * 32
                                      + ((lane >> 3) & 1) * 16;
                        unsigned r[4];
                        ldsm_x4(r, addr);
                        mma_f16(s[2 * ntp],     qf[ks], r[0], r[1]);
                        mma_f16(s[2 * ntp + 1], qf[ks], r[2], r[3]);
                    }
                }

                if (kt >= qt2) {
#pragma unroll
                    for (int nt = 0; nt < 8; nt++) {
                        int key0 = kt * 64 + nt * 8 + 2 * (lane & 3);
                        if (key0     > row_lo)     s[nt][0] = -1e30f;
                        if (key0 + 1 > row_lo)     s[nt][1] = -1e30f;
                        if (key0     > row_lo + 8) s[nt][2] = -1e30f;
                        if (key0 + 1 > row_lo + 8) s[nt][3] = -1e30f;
                    }
                }

                float mloc_lo = -1e30f, mloc_hi = -1e30f;
#pragma unroll
                for (int nt = 0; nt < 8; nt++) {
                    mloc_lo = fmaxf(mloc_lo, fmaxf(s[nt][0], s[nt][1]));
                    mloc_hi = fmaxf(mloc_hi, fmaxf(s[nt][2], s[nt][3]));
                }
                mloc_lo = fmaxf(mloc_lo, __shfl_xor_sync(0xffffffffu, mloc_lo, 1));
                mloc_lo = fmaxf(mloc_lo, __shfl_xor_sync(0xffffffffu, mloc_lo, 2));
                mloc_hi = fmaxf(mloc_hi, __shfl_xor_sync(0xffffffffu, mloc_hi, 1));
                mloc_hi = fmaxf(mloc_hi, __shfl_xor_sync(0xffffffffu, mloc_hi, 2));

                float mn_lo = fmaxf(m_lo, mloc_lo);
                float mn_hi = fmaxf(m_hi, mloc_hi);
                float scl_lo = ex2(m_lo - mn_lo);
                float scl_hi = ex2(m_hi - mn_hi);
                m_lo = mn_lo; m_hi = mn_hi;

                float lloc_lo = 0.0f, lloc_hi = 0.0f;
#pragma unroll
                for (int nt = 0; nt < 8; nt++) {
                    s[nt][0] = ex2(s[nt][0] - m_lo);
                    s[nt][1] = ex2(s[nt][1] - m_lo);
                    s[nt][2] = ex2(s[nt][2] - m_hi);
                    s[nt][3] = ex2(s[nt][3] - m_hi);
                    lloc_lo += s[nt][0] + s[nt][1];
                    lloc_hi += s[nt][2] + s[nt][3];
                }
                lloc_lo += __shfl_xor_sync(0xffffffffu, lloc_lo, 1);
                lloc_lo += __shfl_xor_sync(0xffffffffu, lloc_lo, 2);
                lloc_hi += __shfl_xor_sync(0xffffffffu, lloc_hi, 1);
                lloc_hi += __shfl_xor_sync(0xffffffffu, lloc_hi, 2);
                l_lo = l_lo * scl_lo + lloc_lo;
                l_hi = l_hi * scl_hi + lloc_hi;

#pragma unroll
                for (int nt = 0; nt < 8; nt++) {
                    o[nt][0] *= scl_lo; o[nt][1] *= scl_lo;
                    o[nt][2] *= scl_hi; o[nt][3] *= scl_hi;
                }

#pragma unroll
                for (int ks = 0; ks < 4; ks++) {
                    unsigned pa[4];
                    pa[0] = packh2(s[2 * ks][0],     s[2 * ks][1]);
                    pa[1] = packh2(s[2 * ks][2],     s[2 * ks][3]);
                    pa[2] = packh2(s[2 * ks + 1][0], s[2 * ks + 1][1]);
                    pa[3] = packh2(s[2 * ks + 1][2], s[2 * ks + 1][3]);
#pragma unroll
                    for (int ntp = 0; ntp < 4; ntp++) {
                        int trow = ks * 16 + (lane & 7) + ((lane >> 3) & 1) * 8;
                        unsigned addr = vst + trow * AROW
                                      + (2 * ntp + (lane >> 4)) * 16;
                        unsigned r[4];
                        ldsm_x4_t(r, addr);
                        mma_f16(o[2 * ntp],     pa, r[0], r[1]);
                        mma_f16(o[2 * ntp + 1], pa, r[2], r[3]);
                    }
                }
            }
            __syncthreads();
        }

        float inv_lo = 1.0f / l_lo;
        float inv_hi = 1.0f / l_hi;
        size_t rb_lo = ((size_t)b * S_ + row_lo) * HID_;
        size_t rb_hi = ((size_t)b * S_ + row_lo + 8) * HID_;
#pragma unroll
        for (int nt = 0; nt < 8; nt++) {
            int col = h * 64 + nt * 8 + 2 * (lane & 3);
            *(unsigned*)&Out[rb_lo + col] =
                packh2(o[nt][0] * inv_lo, o[nt][1] * inv_lo);
            *(unsigned*)&Out[rb_hi + col] =
                packh2(o[nt][2] * inv_hi, o[nt][3] * inv_hi);
        }
    }
}

// ---------------- launch ----------------------------------------------------
extern "C" void kernel_launch(void* const* d_in, const int* in_sizes, int n_in,
                              void* d_out, int out_size) {
    const float* hidden  = (const float*)d_in[0];
    const float* w_qkv   = (const float*)d_in[1];
    const float* w_dense = (const float*)d_in[2];
    const float* b_dense = (const float*)d_in[3];
    float* out = (float*)d_out;

    void *p_attno, *p_hid, *p_wqkv, *p_wdense;
    cudaGetSymbolAddress(&p_attno, g_attno);
    cudaGetSymbolAddress(&p_hid, g_hid_h);
    cudaGetSymbolAddress(&p_wqkv, g_wqkv_t);
    cudaGetSymbolAddress(&p_wdense, g_wdense_t);

    // single merged prep: hidden cvt + rope + tickets + both weight transposes
    prep_all_kernel<<<ALL_BLKS, 256>>>(hidden, w_qkv, w_dense);

    size_t gsmem = 4 * GBUF;   // 73728 (2 A bufs + 2 B bufs, BK=64)
    cudaFuncSetAttribute(gemm16_qkv, cudaFuncAttributeMaxDynamicSharedMemorySize,
                         (int)gsmem);
    cudaFuncSetAttribute(gemm16_dense, cudaFuncAttributeMaxDynamicSharedMemorySize,
                         (int)gsmem);

    // persistent QKV GEMM: 296 CTAs, atomic ticket over 768 tiles
    gemm16_qkv<<<296, 256, gsmem>>>((const __half*)p_hid,
                                    (const __half*)p_wqkv);

    {
        size_t asmem = 4 * ABUF;   // 36864 (double-buffered K + V)
        cudaFuncSetAttribute(attn16, cudaFuncAttributeMaxDynamicSharedMemorySize,
                             (int)asmem);
        // persistent attention: 296 CTAs, 512 descending tickets
        attn16<<<296, 256, asmem>>>((__half*)p_attno);
    }

    {
        dim3 grid(HID_ / 128, M_ / 128);
        gemm16_dense<<<grid, 256, gsmem>>>((const __half*)p_attno,
                                           (const __half*)p_wdense, b_dense, out);
    }
}